// round 1
// baseline (speedup 1.0000x reference)
#include <cuda_runtime.h>

#define NN 50000
#define FIN 256
#define NHEADS 4
#define HIDD 32
#define HD 128            // NHEADS*HIDD
#define CC 16
#define EE 1600000
#define EPAD (EE + NN)    // edges + self loops

// ------------------------- scratch (static device globals) -------------------------
__device__ __align__(16) float g_xw1[NN * HD];       // x @ W1
__device__ __align__(16) float g_out1[NN * HD];      // layer-1 aggregated output
__device__ __align__(16) float g_asrc1[NN * NHEADS];
__device__ __align__(16) float g_adst1[NN * NHEADS];
__device__ __align__(16) float g_denom1[NN * NHEADS];
__device__ __align__(16) float g_h2[NN * CC];        // h @ W2
__device__ __align__(16) float g_asrc2[NN];
__device__ __align__(16) float g_adst2[NN];
__device__ __align__(16) float g_denom2[NN];
__device__ __align__(16) float g_out2[NN * CC];
__device__ int g_src[EPAD];
__device__ int g_dst[EPAD];

// ------------------------- helpers -------------------------
__device__ __forceinline__ void red_add_v4(float* p, float4 v) {
    // sm_90+ vectorized global reduction (no return) — 1 instruction per 16B
    asm volatile("red.global.add.v4.f32 [%0], {%1,%2,%3,%4};"
                 :: "l"(p), "f"(v.x), "f"(v.y), "f"(v.z), "f"(v.w)
                 : "memory");
}

__device__ __forceinline__ float leaky(float x) {
    return x > 0.f ? x : 0.2f * x;
}

// ------------------------- kernels -------------------------

// Convert edge_index (int64 OR int32, detected at runtime) to int32 src/dst with
// self-loops appended. For int64 little-endian with ids < 2^31, high words are 0.
__global__ void k_prep(const int* __restrict__ ei) {
    bool is64 = (ei[1] == 0) && (ei[3] == 0) && (ei[5] == 0) && (ei[7] == 0);
    int i = blockIdx.x * blockDim.x + threadIdx.x;
    if (i >= EPAD) return;
    int s, d;
    if (i < EE) {
        if (is64) { s = ei[2 * i]; d = ei[2 * EE + 2 * i]; }
        else      { s = ei[i];     d = ei[EE + i]; }
    } else {
        s = d = i - EE;
    }
    g_src[i] = s;
    g_dst[i] = d;
}

__global__ void k_zero() {
    int i = blockIdx.x * blockDim.x + threadIdx.x;
    if (i < NN * HD) g_out1[i] = 0.f;
    if (i < NN * CC) g_out2[i] = 0.f;
    if (i < NN * NHEADS) g_denom1[i] = 0.f;
    if (i < NN) g_denom2[i] = 0.f;
}

// GEMM1: xw1 = x[N,256] @ W1[256,128].
// Tile 64 rows x 128 cols, 256 threads, each thread 8 rows x 4 cols.
#define KT 32
__global__ __launch_bounds__(256) void k_gemm1(const float* __restrict__ x,
                                               const float* __restrict__ W1) {
    __shared__ float xs[KT][68];    // transposed x tile [k][row], padded
    __shared__ float ws[KT][128];   // W tile [k][col]
    const int m0 = blockIdx.x * 64;
    const int cg = threadIdx.x & 31;   // col group -> cols cg*4 .. +3
    const int rg = threadIdx.x >> 5;   // row group -> rows rg*8 .. +7

    float acc[8][4];
#pragma unroll
    for (int r = 0; r < 8; r++)
#pragma unroll
        for (int c = 0; c < 4; c++) acc[r][c] = 0.f;

    for (int k0 = 0; k0 < FIN; k0 += KT) {
        // load x tile (64 rows x 32 k), coalesced on k
#pragma unroll
        for (int t = 0; t < 8; t++) {
            int idx = threadIdx.x + t * 256;
            int r = idx >> 5, k = idx & 31;
            int row = m0 + r;
            xs[k][r] = (row < NN) ? x[row * FIN + k0 + k] : 0.f;
        }
        // load W tile (32 k x 128 cols), coalesced on col
#pragma unroll
        for (int t = 0; t < 16; t++) {
            int idx = threadIdx.x + t * 256;
            int k = idx >> 7, c = idx & 127;
            ws[k][c] = W1[(k0 + k) * HD + c];
        }
        __syncthreads();
#pragma unroll
        for (int k = 0; k < KT; k++) {
            float4 wv = *(const float4*)&ws[k][cg * 4];
            float xr[8];
            *(float4*)&xr[0] = *(const float4*)&xs[k][rg * 8];
            *(float4*)&xr[4] = *(const float4*)&xs[k][rg * 8 + 4];
#pragma unroll
            for (int r = 0; r < 8; r++) {
                acc[r][0] += xr[r] * wv.x;
                acc[r][1] += xr[r] * wv.y;
                acc[r][2] += xr[r] * wv.z;
                acc[r][3] += xr[r] * wv.w;
            }
        }
        __syncthreads();
    }
#pragma unroll
    for (int r = 0; r < 8; r++) {
        int row = m0 + rg * 8 + r;
        if (row < NN) {
            float4 o = make_float4(acc[r][0], acc[r][1], acc[r][2], acc[r][3]);
            *(float4*)&g_xw1[row * HD + cg * 4] = o;
        }
    }
}

// a_src1/a_dst1: one warp per node; lane i owns dims [4i,4i+4), head = i/8.
__global__ void k_attn1(const float* __restrict__ att_src,
                        const float* __restrict__ att_dst) {
    int t = blockIdx.x * blockDim.x + threadIdx.x;
    int n = t >> 5;
    if (n >= NN) return;
    int lane = t & 31;
    int h = lane >> 3;
    int o = (lane & 7) * 4;
    float4 v = *(const float4*)&g_xw1[n * HD + lane * 4];
    float4 as = *(const float4*)&att_src[h * HIDD + o];
    float4 ad = *(const float4*)&att_dst[h * HIDD + o];
    float ps = v.x * as.x + v.y * as.y + v.z * as.z + v.w * as.w;
    float pd = v.x * ad.x + v.y * ad.y + v.z * ad.z + v.w * ad.w;
#pragma unroll
    for (int off = 4; off; off >>= 1) {
        ps += __shfl_down_sync(0xffffffffu, ps, off);
        pd += __shfl_down_sync(0xffffffffu, pd, off);
    }
    if ((lane & 7) == 0) {
        g_asrc1[n * NHEADS + h] = ps;
        g_adst1[n * NHEADS + h] = pd;
    }
}

// softmax denominator, layer 1 (no max-shift needed: logits are O(10))
__global__ void k_edge_b1() {
    int e = blockIdx.x * blockDim.x + threadIdx.x;
    if (e >= EPAD) return;
    int s = g_src[e], d = g_dst[e];
    float4 as = *(const float4*)&g_asrc1[s * NHEADS];
    float4 ad = *(const float4*)&g_adst1[d * NHEADS];
    float4 ex;
    ex.x = __expf(leaky(as.x + ad.x));
    ex.y = __expf(leaky(as.y + ad.y));
    ex.z = __expf(leaky(as.z + ad.z));
    ex.w = __expf(leaky(as.w + ad.w));
    red_add_v4(&g_denom1[d * NHEADS], ex);
}

// weighted message aggregation, layer 1: one warp per edge, lane i -> dims [4i,4i+4)
__global__ void k_edge_c1() {
    int t = blockIdx.x * blockDim.x + threadIdx.x;
    int e = t >> 5;
    if (e >= EPAD) return;
    int lane = t & 31;
    int s = g_src[e], d = g_dst[e];
    int h = lane >> 3;
    float ev = leaky(g_asrc1[s * NHEADS + h] + g_adst1[d * NHEADS + h]);
    float alpha = __fdividef(__expf(ev), g_denom1[d * NHEADS + h]);
    float4 v = *(const float4*)&g_xw1[s * HD + lane * 4];
    v.x *= alpha; v.y *= alpha; v.z *= alpha; v.w *= alpha;
    red_add_v4(&g_out1[d * HD + lane * 4], v);
}

// bias+relu, GEMM2 (128->16), and layer-2 attention coefficients. One warp/node.
__global__ void k_layer2(const float* __restrict__ b1,
                         const float* __restrict__ W2,
                         const float* __restrict__ as2,
                         const float* __restrict__ ad2) {
    int t = blockIdx.x * blockDim.x + threadIdx.x;
    int n = t >> 5;
    if (n >= NN) return;
    int lane = t & 31;
    float4 hv = *(const float4*)&g_out1[n * HD + lane * 4];
    float4 bv = *(const float4*)&b1[lane * 4];
    hv.x = fmaxf(hv.x + bv.x, 0.f);
    hv.y = fmaxf(hv.y + bv.y, 0.f);
    hv.z = fmaxf(hv.z + bv.z, 0.f);
    hv.w = fmaxf(hv.w + bv.w, 0.f);
    float asum = 0.f, dsum = 0.f;
#pragma unroll
    for (int c = 0; c < CC; c++) {
        const float* w = &W2[(lane * 4) * CC + c];
        float p = hv.x * w[0] + hv.y * w[CC] + hv.z * w[2 * CC] + hv.w * w[3 * CC];
#pragma unroll
        for (int off = 16; off; off >>= 1)
            p += __shfl_down_sync(0xffffffffu, p, off);
        if (lane == 0) {
            g_h2[n * CC + c] = p;
            asum += p * as2[c];
            dsum += p * ad2[c];
        }
    }
    if (lane == 0) {
        g_asrc2[n] = asum;
        g_adst2[n] = dsum;
    }
}

__global__ void k_edge_b2() {
    int e = blockIdx.x * blockDim.x + threadIdx.x;
    if (e >= EPAD) return;
    int s = g_src[e], d = g_dst[e];
    float ev = leaky(g_asrc2[s] + g_adst2[d]);
    atomicAdd(&g_denom2[d], __expf(ev));
}

// layer-2 aggregation: 4 lanes per edge, each lane one float4 of the 16-dim msg
__global__ void k_edge_c2() {
    int t = blockIdx.x * blockDim.x + threadIdx.x;
    int e = t >> 2;
    if (e >= EPAD) return;
    int j = t & 3;
    int s = g_src[e], d = g_dst[e];
    float ev = leaky(g_asrc2[s] + g_adst2[d]);
    float alpha = __fdividef(__expf(ev), g_denom2[d]);
    float4 v = *(const float4*)&g_h2[s * CC + j * 4];
    v.x *= alpha; v.y *= alpha; v.z *= alpha; v.w *= alpha;
    red_add_v4(&g_out2[d * CC + j * 4], v);
}

// bias + log_softmax over 16 classes, one thread per node
__global__ void k_final(const float* __restrict__ b2, float* __restrict__ out) {
    int n = blockIdx.x * blockDim.x + threadIdx.x;
    if (n >= NN) return;
    float v[CC];
#pragma unroll
    for (int j = 0; j < 4; j++) {
        float4 tv = *(const float4*)&g_out2[n * CC + j * 4];
        float4 bb = *(const float4*)&b2[j * 4];
        v[j * 4 + 0] = tv.x + bb.x;
        v[j * 4 + 1] = tv.y + bb.y;
        v[j * 4 + 2] = tv.z + bb.z;
        v[j * 4 + 3] = tv.w + bb.w;
    }
    float m = v[0];
#pragma unroll
    for (int c = 1; c < CC; c++) m = fmaxf(m, v[c]);
    float s = 0.f;
#pragma unroll
    for (int c = 0; c < CC; c++) s += __expf(v[c] - m);
    float l = m + logf(s);
#pragma unroll
    for (int j = 0; j < 4; j++) {
        float4 o;
        o.x = v[j * 4 + 0] - l;
        o.y = v[j * 4 + 1] - l;
        o.z = v[j * 4 + 2] - l;
        o.w = v[j * 4 + 3] - l;
        *(float4*)&out[n * CC + j * 4] = o;
    }
}

// ------------------------- launch -------------------------
extern "C" void kernel_launch(void* const* d_in, const int* in_sizes, int n_in,
                              void* d_out, int out_size) {
    const float* x    = (const float*)d_in[0];
    const int*   ei   = (const int*)d_in[1];
    const float* W1   = (const float*)d_in[2];
    const float* as1  = (const float*)d_in[3];
    const float* ad1  = (const float*)d_in[4];
    const float* b1   = (const float*)d_in[5];
    const float* W2   = (const float*)d_in[6];
    const float* as2  = (const float*)d_in[7];
    const float* ad2  = (const float*)d_in[8];
    const float* b2   = (const float*)d_in[9];
    float* out = (float*)d_out;

    k_prep<<<(EPAD + 255) / 256, 256>>>(ei);
    k_zero<<<(NN * HD + 255) / 256, 256>>>();
    k_gemm1<<<(NN + 63) / 64, 256>>>(x, W1);
    k_attn1<<<(NN * 32 + 255) / 256, 256>>>(as1, ad1);
    k_edge_b1<<<(EPAD + 255) / 256, 256>>>();
    {
        long long tt = (long long)EPAD * 32;
        k_edge_c1<<<(unsigned)((tt + 255) / 256), 256>>>();
    }
    k_layer2<<<(NN * 32 + 255) / 256, 256>>>(b1, W2, as2, ad2);
    k_edge_b2<<<(EPAD + 255) / 256, 256>>>();
    k_edge_c2<<<(EPAD * 4 + 255) / 256, 256>>>();
    k_final<<<(NN + 255) / 256, 256>>>(b2, out);
}

// round 2
// speedup vs baseline: 2.7908x; 2.7908x over previous
#include <cuda_runtime.h>

#define NN 50000
#define FIN 256
#define NHEADS 4
#define HIDD 32
#define HD 128            // NHEADS*HIDD
#define CC 16
#define EE 1600000
#define EPAD (EE + NN)    // edges + self loops
#define NB1 ((NN + 1023) / 1024)

// ------------------------- scratch (static device globals) -------------------------
__device__ __align__(16) float g_xw1[NN * HD];       // x @ W1
__device__ __align__(16) float g_asrc1[NN * NHEADS];
__device__ __align__(16) float g_adst1[NN * NHEADS];
__device__ __align__(16) float g_h2[NN * CC];        // relu(agg1+b1) @ W2
__device__ __align__(16) float g_asrc2[NN];
__device__ __align__(16) float g_adst2[NN];
__device__ __align__(16) float g_out2[NN * CC];
__device__ int g_src[EPAD];
__device__ int g_dst[EPAD];
__device__ int g_csrc[EPAD];     // src ids sorted by dst (CSR col indices)
__device__ int g_deg[NN];
__device__ int g_rowptr[NN + 1];
__device__ int g_cursor[NN];
__device__ int g_bsum[64];

__device__ __forceinline__ float leaky(float x) { return x > 0.f ? x : 0.2f * x; }

// ------------------------- graph prep -------------------------
__global__ void k_zero0() {
    int i = blockIdx.x * blockDim.x + threadIdx.x;
    if (i < NN) g_deg[i] = 0;
}

// edge_index (int64 or int32, runtime detect) -> src/dst int32 + dst histogram
__global__ void k_prep(const int* __restrict__ ei) {
    bool is64 = (ei[1] == 0) && (ei[3] == 0) && (ei[5] == 0) && (ei[7] == 0);
    int i = blockIdx.x * blockDim.x + threadIdx.x;
    if (i >= EPAD) return;
    int s, d;
    if (i < EE) {
        if (is64) { s = ei[2 * i]; d = ei[2 * EE + 2 * i]; }
        else      { s = ei[i];     d = ei[EE + i]; }
    } else {
        s = d = i - EE;
    }
    g_src[i] = s;
    g_dst[i] = d;
    atomicAdd(&g_deg[d], 1);
}

// block-wise exclusive scan of degrees (1024/block)
__global__ __launch_bounds__(1024) void k_scan1() {
    int t = threadIdx.x, b = blockIdx.x;
    int i = b * 1024 + t;
    int val = (i < NN) ? g_deg[i] : 0;
    int lane = t & 31, wid = t >> 5;
    int x = val;
#pragma unroll
    for (int off = 1; off < 32; off <<= 1) {
        int y = __shfl_up_sync(0xffffffffu, x, off);
        if (lane >= off) x += y;
    }
    __shared__ int wsum[32];
    if (lane == 31) wsum[wid] = x;
    __syncthreads();
    if (wid == 0) {
        int w = wsum[lane];
#pragma unroll
        for (int off = 1; off < 32; off <<= 1) {
            int y = __shfl_up_sync(0xffffffffu, w, off);
            if (lane >= off) w += y;
        }
        wsum[lane] = w;
    }
    __syncthreads();
    int incl = x + (wid > 0 ? wsum[wid - 1] : 0);
    if (i < NN) g_rowptr[i] = incl - val;
    if (t == 1023) g_bsum[b] = incl;
}

__global__ void k_scan2() {
    __shared__ int s[64];
    int t = threadIdx.x;
    s[t] = (t < NB1) ? g_bsum[t] : 0;
    __syncthreads();
    if (t == 0) {
        int run = 0;
        for (int i = 0; i < NB1; i++) { int v = s[i]; s[i] = run; run += v; }
    }
    __syncthreads();
    if (t < NB1) g_bsum[t] = s[t];
}

__global__ void k_scan3() {
    int i = blockIdx.x * blockDim.x + threadIdx.x;
    if (i < NN) {
        int v = g_rowptr[i] + g_bsum[i >> 10];
        g_rowptr[i] = v;
        g_cursor[i] = v;
    }
    if (i == 0) g_rowptr[NN] = EPAD;
}

__global__ void k_scatter() {
    int i = blockIdx.x * blockDim.x + threadIdx.x;
    if (i >= EPAD) return;
    int d = g_dst[i];
    int pos = atomicAdd(&g_cursor[d], 1);
    g_csrc[pos] = g_src[i];
}

// ------------------------- GEMM1 (f32x2 packed) + fused attn coefficients -------------------------
#define KT 32
__global__ __launch_bounds__(256) void k_gemm1(const float* __restrict__ x,
                                               const float* __restrict__ W1,
                                               const float* __restrict__ att_src,
                                               const float* __restrict__ att_dst) {
    __shared__ __align__(16) float xs[KT][68];   // [k][row], padded
    __shared__ __align__(16) float ws[KT][128];  // [k][col]
    const int m0 = blockIdx.x * 64;
    const int cg = threadIdx.x & 31;   // lane: cols cg*4..+3
    const int rg = threadIdx.x >> 5;   // warp: rows rg*8..+7

    unsigned long long acc2[4][4];     // row-pairs x 4 cols, packed f32x2
#pragma unroll
    for (int p = 0; p < 4; p++)
#pragma unroll
        for (int c = 0; c < 4; c++) acc2[p][c] = 0ULL;

    for (int k0 = 0; k0 < FIN; k0 += KT) {
#pragma unroll
        for (int t = 0; t < 8; t++) {
            int idx = threadIdx.x + t * 256;
            int r = idx >> 5, k = idx & 31;
            int row = m0 + r;
            xs[k][r] = (row < NN) ? x[row * FIN + k0 + k] : 0.f;
        }
#pragma unroll
        for (int t = 0; t < 16; t++) {
            int idx = threadIdx.x + t * 256;
            int k = idx >> 7, c = idx & 127;
            ws[k][c] = W1[(k0 + k) * HD + c];
        }
        __syncthreads();
#pragma unroll
        for (int k = 0; k < KT; k++) {
            float4 wv = *(const float4*)&ws[k][cg * 4];
            unsigned long long wp[4];
            asm("mov.b64 %0, {%1, %1};" : "=l"(wp[0]) : "r"(__float_as_uint(wv.x)));
            asm("mov.b64 %0, {%1, %1};" : "=l"(wp[1]) : "r"(__float_as_uint(wv.y)));
            asm("mov.b64 %0, {%1, %1};" : "=l"(wp[2]) : "r"(__float_as_uint(wv.z)));
            asm("mov.b64 %0, {%1, %1};" : "=l"(wp[3]) : "r"(__float_as_uint(wv.w)));
            unsigned long long xp[4];
#pragma unroll
            for (int p = 0; p < 4; p++)
                xp[p] = *(const unsigned long long*)&xs[k][rg * 8 + 2 * p];
#pragma unroll
            for (int p = 0; p < 4; p++)
#pragma unroll
                for (int c = 0; c < 4; c++)
                    asm("fma.rn.f32x2 %0, %1, %2, %0;"
                        : "+l"(acc2[p][c]) : "l"(xp[p]), "l"(wp[c]));
        }
        __syncthreads();
    }

    // unpack
    float acc[8][4];
#pragma unroll
    for (int p = 0; p < 4; p++)
#pragma unroll
        for (int c = 0; c < 4; c++) {
            float lo, hi;
            asm("mov.b64 {%0, %1}, %2;" : "=f"(lo), "=f"(hi) : "l"(acc2[p][c]));
            acc[2 * p][c] = lo;
            acc[2 * p + 1][c] = hi;
        }

    const int h = cg >> 3;
    const int o = (cg & 7) * 4;
    float4 asv = *(const float4*)&att_src[h * HIDD + o];
    float4 adv = *(const float4*)&att_dst[h * HIDD + o];

#pragma unroll
    for (int r = 0; r < 8; r++) {
        int row = m0 + rg * 8 + r;
        bool ok = row < NN;
        if (ok) {
            float4 ov = make_float4(acc[r][0], acc[r][1], acc[r][2], acc[r][3]);
            *(float4*)&g_xw1[row * HD + cg * 4] = ov;
        }
        float ps = acc[r][0] * asv.x + acc[r][1] * asv.y + acc[r][2] * asv.z + acc[r][3] * asv.w;
        float pd = acc[r][0] * adv.x + acc[r][1] * adv.y + acc[r][2] * adv.z + acc[r][3] * adv.w;
#pragma unroll
        for (int off = 4; off; off >>= 1) {
            ps += __shfl_down_sync(0xffffffffu, ps, off, 8);
            pd += __shfl_down_sync(0xffffffffu, pd, off, 8);
        }
        if (ok && (cg & 7) == 0) {
            g_asrc1[row * NHEADS + h] = ps;
            g_adst1[row * NHEADS + h] = pd;
        }
    }
}

// ------------------------- layer-1 aggregation (fused softmax + bias/relu + GEMM2 + attn2) ----
__global__ __launch_bounds__(256) void k_agg1(const float* __restrict__ b1,
                                              const float* __restrict__ W2,
                                              const float* __restrict__ as2,
                                              const float* __restrict__ ad2) {
    __shared__ float w2s[CC * HD];   // transposed: w2s[c*128 + d] = W2[d*16+c]
    for (int idx = threadIdx.x; idx < CC * HD; idx += 256) {
        int dcol = idx & 15, drow = idx >> 4;
        w2s[dcol * HD + drow] = W2[idx];
    }
    __syncthreads();

    int t = blockIdx.x * 256 + threadIdx.x;
    int n = t >> 5;
    int lane = t & 31;
    if (n >= NN) return;

    const int h = lane >> 3;
    const float adst = g_adst1[n * NHEADS + h];
    int p = g_rowptr[n], p1 = g_rowptr[n + 1];

    float ax = 0.f, ay = 0.f, az = 0.f, aw = 0.f, den = 0.f;
    for (; p + 4 <= p1; p += 4) {
        int s0 = g_csrc[p], s1 = g_csrc[p + 1], s2 = g_csrc[p + 2], s3 = g_csrc[p + 3];
        float a0 = g_asrc1[s0 * NHEADS + h];
        float a1 = g_asrc1[s1 * NHEADS + h];
        float a2 = g_asrc1[s2 * NHEADS + h];
        float a3 = g_asrc1[s3 * NHEADS + h];
        float4 v0 = *(const float4*)&g_xw1[s0 * HD + lane * 4];
        float4 v1 = *(const float4*)&g_xw1[s1 * HD + lane * 4];
        float4 v2 = *(const float4*)&g_xw1[s2 * HD + lane * 4];
        float4 v3 = *(const float4*)&g_xw1[s3 * HD + lane * 4];
        float e0 = __expf(leaky(a0 + adst));
        float e1 = __expf(leaky(a1 + adst));
        float e2 = __expf(leaky(a2 + adst));
        float e3 = __expf(leaky(a3 + adst));
        den += e0 + e1 + e2 + e3;
        ax = fmaf(e0, v0.x, fmaf(e1, v1.x, fmaf(e2, v2.x, fmaf(e3, v3.x, ax))));
        ay = fmaf(e0, v0.y, fmaf(e1, v1.y, fmaf(e2, v2.y, fmaf(e3, v3.y, ay))));
        az = fmaf(e0, v0.z, fmaf(e1, v1.z, fmaf(e2, v2.z, fmaf(e3, v3.z, az))));
        aw = fmaf(e0, v0.w, fmaf(e1, v1.w, fmaf(e2, v2.w, fmaf(e3, v3.w, aw))));
    }
    for (; p < p1; p++) {
        int s0 = g_csrc[p];
        float a0 = g_asrc1[s0 * NHEADS + h];
        float4 v0 = *(const float4*)&g_xw1[s0 * HD + lane * 4];
        float e0 = __expf(leaky(a0 + adst));
        den += e0;
        ax = fmaf(e0, v0.x, ax);
        ay = fmaf(e0, v0.y, ay);
        az = fmaf(e0, v0.z, az);
        aw = fmaf(e0, v0.w, aw);
    }
    float inv = __fdividef(1.f, den);
    float4 bv = *(const float4*)&b1[lane * 4];
    float4 hv;
    hv.x = fmaxf(fmaf(ax, inv, bv.x), 0.f);
    hv.y = fmaxf(fmaf(ay, inv, bv.y), 0.f);
    hv.z = fmaxf(fmaf(az, inv, bv.z), 0.f);
    hv.w = fmaxf(fmaf(aw, inv, bv.w), 0.f);

    // h @ W2 (128->16) + layer-2 attention coefficients
    float asum = 0.f, dsum = 0.f;
#pragma unroll
    for (int c = 0; c < CC; c++) {
        float4 wv = *(const float4*)&w2s[c * HD + lane * 4];
        float pp = hv.x * wv.x + hv.y * wv.y + hv.z * wv.z + hv.w * wv.w;
#pragma unroll
        for (int off = 16; off; off >>= 1)
            pp += __shfl_down_sync(0xffffffffu, pp, off);
        if (lane == 0) {
            g_h2[n * CC + c] = pp;
            asum = fmaf(pp, as2[c], asum);
            dsum = fmaf(pp, ad2[c], dsum);
        }
    }
    if (lane == 0) {
        g_asrc2[n] = asum;
        g_adst2[n] = dsum;
    }
}

// ------------------------- layer-2 aggregation (4 lanes/node) -------------------------
__global__ void k_agg2() {
    int t = blockIdx.x * blockDim.x + threadIdx.x;
    int n = t >> 2;
    if (n >= NN) return;
    int j = t & 3;
    const float adst = g_adst2[n];
    int p = g_rowptr[n], p1 = g_rowptr[n + 1];
    float ax = 0.f, ay = 0.f, az = 0.f, aw = 0.f, den = 0.f;
    for (; p + 4 <= p1; p += 4) {
        int s0 = g_csrc[p], s1 = g_csrc[p + 1], s2 = g_csrc[p + 2], s3 = g_csrc[p + 3];
        float a0 = g_asrc2[s0], a1 = g_asrc2[s1], a2 = g_asrc2[s2], a3 = g_asrc2[s3];
        float4 v0 = *(const float4*)&g_h2[s0 * CC + j * 4];
        float4 v1 = *(const float4*)&g_h2[s1 * CC + j * 4];
        float4 v2 = *(const float4*)&g_h2[s2 * CC + j * 4];
        float4 v3 = *(const float4*)&g_h2[s3 * CC + j * 4];
        float e0 = __expf(leaky(a0 + adst));
        float e1 = __expf(leaky(a1 + adst));
        float e2 = __expf(leaky(a2 + adst));
        float e3 = __expf(leaky(a3 + adst));
        den += e0 + e1 + e2 + e3;
        ax = fmaf(e0, v0.x, fmaf(e1, v1.x, fmaf(e2, v2.x, fmaf(e3, v3.x, ax))));
        ay = fmaf(e0, v0.y, fmaf(e1, v1.y, fmaf(e2, v2.y, fmaf(e3, v3.y, ay))));
        az = fmaf(e0, v0.z, fmaf(e1, v1.z, fmaf(e2, v2.z, fmaf(e3, v3.z, az))));
        aw = fmaf(e0, v0.w, fmaf(e1, v1.w, fmaf(e2, v2.w, fmaf(e3, v3.w, aw))));
    }
    for (; p < p1; p++) {
        int s0 = g_csrc[p];
        float a0 = g_asrc2[s0];
        float4 v0 = *(const float4*)&g_h2[s0 * CC + j * 4];
        float e0 = __expf(leaky(a0 + adst));
        den += e0;
        ax = fmaf(e0, v0.x, ax);
        ay = fmaf(e0, v0.y, ay);
        az = fmaf(e0, v0.z, az);
        aw = fmaf(e0, v0.w, aw);
    }
    float inv = __fdividef(1.f, den);
    float4 o = make_float4(ax * inv, ay * inv, az * inv, aw * inv);
    *(float4*)&g_out2[n * CC + j * 4] = o;
}

// ------------------------- bias + log_softmax -------------------------
__global__ void k_final(const float* __restrict__ b2, float* __restrict__ out) {
    int n = blockIdx.x * blockDim.x + threadIdx.x;
    if (n >= NN) return;
    float v[CC];
#pragma unroll
    for (int j = 0; j < 4; j++) {
        float4 tv = *(const float4*)&g_out2[n * CC + j * 4];
        float4 bb = *(const float4*)&b2[j * 4];
        v[j * 4 + 0] = tv.x + bb.x;
        v[j * 4 + 1] = tv.y + bb.y;
        v[j * 4 + 2] = tv.z + bb.z;
        v[j * 4 + 3] = tv.w + bb.w;
    }
    float m = v[0];
#pragma unroll
    for (int c = 1; c < CC; c++) m = fmaxf(m, v[c]);
    float s = 0.f;
#pragma unroll
    for (int c = 0; c < CC; c++) s += __expf(v[c] - m);
    float l = m + logf(s);
#pragma unroll
    for (int j = 0; j < 4; j++) {
        float4 o;
        o.x = v[j * 4 + 0] - l;
        o.y = v[j * 4 + 1] - l;
        o.z = v[j * 4 + 2] - l;
        o.w = v[j * 4 + 3] - l;
        *(float4*)&out[n * CC + j * 4] = o;
    }
}

// ------------------------- launch -------------------------
extern "C" void kernel_launch(void* const* d_in, const int* in_sizes, int n_in,
                              void* d_out, int out_size) {
    const float* x   = (const float*)d_in[0];
    const int*   ei  = (const int*)d_in[1];
    const float* W1  = (const float*)d_in[2];
    const float* as1 = (const float*)d_in[3];
    const float* ad1 = (const float*)d_in[4];
    const float* b1  = (const float*)d_in[5];
    const float* W2  = (const float*)d_in[6];
    const float* as2 = (const float*)d_in[7];
    const float* ad2 = (const float*)d_in[8];
    const float* b2  = (const float*)d_in[9];
    float* out = (float*)d_out;

    k_zero0<<<(NN + 255) / 256, 256>>>();
    k_prep<<<(EPAD + 255) / 256, 256>>>(ei);
    k_scan1<<<NB1, 1024>>>();
    k_scan2<<<1, 64>>>();
    k_scan3<<<(NN + 255) / 256, 256>>>();
    k_scatter<<<(EPAD + 255) / 256, 256>>>();
    k_gemm1<<<(NN + 63) / 64, 256>>>(x, W1, as1, ad1);
    k_agg1<<<(NN * 32 + 255) / 256, 256>>>(b1, W2, as2, ad2);
    k_agg2<<<(NN * 4 + 255) / 256, 256>>>();
    k_final<<<(NN + 255) / 256, 256>>>(b2, out);
}

// round 3
// speedup vs baseline: 3.3002x; 1.1825x over previous
#include <cuda_runtime.h>
#include <cuda_fp16.h>

#define NN 50000
#define FIN 256
#define NHEADS 4
#define HIDD 32
#define HD 128            // NHEADS*HIDD
#define CC 16
#define EE 1600000
#define EPAD (EE + NN)    // edges + self loops
#define NB1 ((NN + 1023) / 1024)

// ------------------------- scratch (static device globals) -------------------------
__device__ __align__(16) __half g_xw1h[NN * HD];     // x @ W1 (fp16 copy for gather)
__device__ __align__(16) float g_asrc1[NN * NHEADS];
__device__ __align__(16) float g_adst1[NN * NHEADS];
__device__ __align__(16) __half g_h2h[NN * CC];      // relu(agg1+b1) @ W2, fp16
__device__ __align__(16) float g_asrc2[NN];
__device__ __align__(16) float g_adst2[NN];
__device__ int g_src[EPAD];
__device__ int g_dst[EPAD];
__device__ int g_csrc[EPAD];     // src ids sorted by dst (CSR col indices)
__device__ int g_deg[NN];
__device__ int g_rowptr[NN + 1];
__device__ int g_cursor[NN];
__device__ int g_bsum[64];

__device__ __forceinline__ float leaky(float x) { return x > 0.f ? x : 0.2f * x; }

// ------------------------- graph prep -------------------------
// edge_index (int64 or int32, runtime detect) -> src/dst int32 + dst histogram
__global__ void k_prep(const int* __restrict__ ei) {
    bool is64 = (ei[1] == 0) && (ei[3] == 0) && (ei[5] == 0) && (ei[7] == 0);
    int i = blockIdx.x * blockDim.x + threadIdx.x;
    if (i >= EPAD) return;
    int s, d;
    if (i < EE) {
        if (is64) { s = ei[2 * i]; d = ei[2 * EE + 2 * i]; }
        else      { s = ei[i];     d = ei[EE + i]; }
    } else {
        s = d = i - EE;
    }
    g_src[i] = s;
    g_dst[i] = d;
    atomicAdd(&g_deg[d], 1);
}

// block-wise exclusive scan of degrees (1024/block)
__global__ __launch_bounds__(1024) void k_scan1() {
    int t = threadIdx.x, b = blockIdx.x;
    int i = b * 1024 + t;
    int val = (i < NN) ? g_deg[i] : 0;
    int lane = t & 31, wid = t >> 5;
    int x = val;
#pragma unroll
    for (int off = 1; off < 32; off <<= 1) {
        int y = __shfl_up_sync(0xffffffffu, x, off);
        if (lane >= off) x += y;
    }
    __shared__ int wsum[32];
    if (lane == 31) wsum[wid] = x;
    __syncthreads();
    if (wid == 0) {
        int w = wsum[lane];
#pragma unroll
        for (int off = 1; off < 32; off <<= 1) {
            int y = __shfl_up_sync(0xffffffffu, w, off);
            if (lane >= off) w += y;
        }
        wsum[lane] = w;
    }
    __syncthreads();
    int incl = x + (wid > 0 ? wsum[wid - 1] : 0);
    if (i < NN) g_rowptr[i] = incl - val;
    if (t == 1023) g_bsum[b] = incl;
}

__global__ void k_scan2() {
    __shared__ int s[64];
    int t = threadIdx.x;
    s[t] = (t < NB1) ? g_bsum[t] : 0;
    __syncthreads();
    if (t == 0) {
        int run = 0;
        for (int i = 0; i < NB1; i++) { int v = s[i]; s[i] = run; run += v; }
    }
    __syncthreads();
    if (t < NB1) g_bsum[t] = s[t];
}

__global__ void k_scan3() {
    int i = blockIdx.x * blockDim.x + threadIdx.x;
    if (i < NN) {
        int v = g_rowptr[i] + g_bsum[i >> 10];
        g_rowptr[i] = v;
        g_cursor[i] = v;
    }
    if (i == 0) g_rowptr[NN] = EPAD;
}

__global__ void k_scatter() {
    int i = blockIdx.x * blockDim.x + threadIdx.x;
    if (i >= EPAD) return;
    int d = g_dst[i];
    int pos = atomicAdd(&g_cursor[d], 1);
    g_csrc[pos] = g_src[i];
}

// ------------------------- GEMM1 (f32x2 packed) + fused attn coefficients -------------------------
#define KT 32
__global__ __launch_bounds__(256) void k_gemm1(const float* __restrict__ x,
                                               const float* __restrict__ W1,
                                               const float* __restrict__ att_src,
                                               const float* __restrict__ att_dst) {
    __shared__ __align__(16) float xs[KT][68];   // [k][row], padded
    __shared__ __align__(16) float ws[KT][128];  // [k][col]
    const int m0 = blockIdx.x * 64;
    const int cg = threadIdx.x & 31;   // lane: cols cg*4..+3
    const int rg = threadIdx.x >> 5;   // warp: rows rg*8..+7

    unsigned long long acc2[4][4];     // row-pairs x 4 cols, packed f32x2
#pragma unroll
    for (int p = 0; p < 4; p++)
#pragma unroll
        for (int c = 0; c < 4; c++) acc2[p][c] = 0ULL;

    for (int k0 = 0; k0 < FIN; k0 += KT) {
#pragma unroll
        for (int t = 0; t < 8; t++) {
            int idx = threadIdx.x + t * 256;
            int r = idx >> 5, k = idx & 31;
            int row = m0 + r;
            xs[k][r] = (row < NN) ? x[row * FIN + k0 + k] : 0.f;
        }
#pragma unroll
        for (int t = 0; t < 16; t++) {
            int idx = threadIdx.x + t * 256;
            int k = idx >> 7, c = idx & 127;
            ws[k][c] = W1[(k0 + k) * HD + c];
        }
        __syncthreads();
#pragma unroll
        for (int k = 0; k < KT; k++) {
            float4 wv = *(const float4*)&ws[k][cg * 4];
            unsigned long long wp[4];
            asm("mov.b64 %0, {%1, %1};" : "=l"(wp[0]) : "r"(__float_as_uint(wv.x)));
            asm("mov.b64 %0, {%1, %1};" : "=l"(wp[1]) : "r"(__float_as_uint(wv.y)));
            asm("mov.b64 %0, {%1, %1};" : "=l"(wp[2]) : "r"(__float_as_uint(wv.z)));
            asm("mov.b64 %0, {%1, %1};" : "=l"(wp[3]) : "r"(__float_as_uint(wv.w)));
            unsigned long long xp[4];
#pragma unroll
            for (int p = 0; p < 4; p++)
                xp[p] = *(const unsigned long long*)&xs[k][rg * 8 + 2 * p];
#pragma unroll
            for (int p = 0; p < 4; p++)
#pragma unroll
                for (int c = 0; c < 4; c++)
                    asm("fma.rn.f32x2 %0, %1, %2, %0;"
                        : "+l"(acc2[p][c]) : "l"(xp[p]), "l"(wp[c]));
        }
        __syncthreads();
    }

    // unpack
    float acc[8][4];
#pragma unroll
    for (int p = 0; p < 4; p++)
#pragma unroll
        for (int c = 0; c < 4; c++) {
            float lo, hi;
            asm("mov.b64 {%0, %1}, %2;" : "=f"(lo), "=f"(hi) : "l"(acc2[p][c]));
            acc[2 * p][c] = lo;
            acc[2 * p + 1][c] = hi;
        }

    const int h = cg >> 3;
    const int o = (cg & 7) * 4;
    float4 asv = *(const float4*)&att_src[h * HIDD + o];
    float4 adv = *(const float4*)&att_dst[h * HIDD + o];

#pragma unroll
    for (int r = 0; r < 8; r++) {
        int row = m0 + rg * 8 + r;
        bool ok = row < NN;
        if (ok) {
            __half2 h01 = __floats2half2_rn(acc[r][0], acc[r][1]);
            __half2 h23 = __floats2half2_rn(acc[r][2], acc[r][3]);
            uint2 u = make_uint2(*(unsigned*)&h01, *(unsigned*)&h23);
            *(uint2*)&g_xw1h[row * HD + cg * 4] = u;
        }
        float ps = acc[r][0] * asv.x + acc[r][1] * asv.y + acc[r][2] * asv.z + acc[r][3] * asv.w;
        float pd = acc[r][0] * adv.x + acc[r][1] * adv.y + acc[r][2] * adv.z + acc[r][3] * adv.w;
#pragma unroll
        for (int off = 4; off; off >>= 1) {
            ps += __shfl_down_sync(0xffffffffu, ps, off, 8);
            pd += __shfl_down_sync(0xffffffffu, pd, off, 8);
        }
        if (ok && (cg & 7) == 0) {
            g_asrc1[row * NHEADS + h] = ps;
            g_adst1[row * NHEADS + h] = pd;
        }
    }
}

// ------------------------- layer-1 aggregation (fused softmax + bias/relu + GEMM2 + attn2) ----
__device__ __forceinline__ void h4_to_f4(uint2 u, float& a, float& b, float& c, float& d) {
    float2 lo = __half22float2(*(__half2*)&u.x);
    float2 hi = __half22float2(*(__half2*)&u.y);
    a = lo.x; b = lo.y; c = hi.x; d = hi.y;
}

__global__ __launch_bounds__(256) void k_agg1(const float* __restrict__ b1,
                                              const float* __restrict__ W2,
                                              const float* __restrict__ as2,
                                              const float* __restrict__ ad2) {
    __shared__ float w2s[CC * HD];   // transposed: w2s[c*128 + d] = W2[d*16+c]
    for (int idx = threadIdx.x; idx < CC * HD; idx += 256) {
        int dcol = idx & 15, drow = idx >> 4;
        w2s[dcol * HD + drow] = W2[idx];
    }
    __syncthreads();

    int t = blockIdx.x * 256 + threadIdx.x;
    int n = t >> 5;
    int lane = t & 31;
    if (n >= NN) return;

    const int h = lane >> 3;
    const float adst = g_adst1[n * NHEADS + h];
    int p = g_rowptr[n], p1 = g_rowptr[n + 1];

    float ax = 0.f, ay = 0.f, az = 0.f, aw = 0.f, den = 0.f;
    for (; p + 4 <= p1; p += 4) {
        int s0 = g_csrc[p], s1 = g_csrc[p + 1], s2 = g_csrc[p + 2], s3 = g_csrc[p + 3];
        float a0 = g_asrc1[s0 * NHEADS + h];
        float a1 = g_asrc1[s1 * NHEADS + h];
        float a2 = g_asrc1[s2 * NHEADS + h];
        float a3 = g_asrc1[s3 * NHEADS + h];
        uint2 u0 = *(const uint2*)&g_xw1h[s0 * HD + lane * 4];
        uint2 u1 = *(const uint2*)&g_xw1h[s1 * HD + lane * 4];
        uint2 u2 = *(const uint2*)&g_xw1h[s2 * HD + lane * 4];
        uint2 u3 = *(const uint2*)&g_xw1h[s3 * HD + lane * 4];
        float e0 = __expf(leaky(a0 + adst));
        float e1 = __expf(leaky(a1 + adst));
        float e2 = __expf(leaky(a2 + adst));
        float e3 = __expf(leaky(a3 + adst));
        den += e0 + e1 + e2 + e3;
        float vx, vy, vz, vw;
        h4_to_f4(u0, vx, vy, vz, vw);
        ax = fmaf(e0, vx, ax); ay = fmaf(e0, vy, ay); az = fmaf(e0, vz, az); aw = fmaf(e0, vw, aw);
        h4_to_f4(u1, vx, vy, vz, vw);
        ax = fmaf(e1, vx, ax); ay = fmaf(e1, vy, ay); az = fmaf(e1, vz, az); aw = fmaf(e1, vw, aw);
        h4_to_f4(u2, vx, vy, vz, vw);
        ax = fmaf(e2, vx, ax); ay = fmaf(e2, vy, ay); az = fmaf(e2, vz, az); aw = fmaf(e2, vw, aw);
        h4_to_f4(u3, vx, vy, vz, vw);
        ax = fmaf(e3, vx, ax); ay = fmaf(e3, vy, ay); az = fmaf(e3, vz, az); aw = fmaf(e3, vw, aw);
    }
    for (; p < p1; p++) {
        int s0 = g_csrc[p];
        float a0 = g_asrc1[s0 * NHEADS + h];
        uint2 u0 = *(const uint2*)&g_xw1h[s0 * HD + lane * 4];
        float e0 = __expf(leaky(a0 + adst));
        den += e0;
        float vx, vy, vz, vw;
        h4_to_f4(u0, vx, vy, vz, vw);
        ax = fmaf(e0, vx, ax); ay = fmaf(e0, vy, ay); az = fmaf(e0, vz, az); aw = fmaf(e0, vw, aw);
    }
    float inv = __fdividef(1.f, den);
    float4 bv = *(const float4*)&b1[lane * 4];
    float4 hv;
    hv.x = fmaxf(fmaf(ax, inv, bv.x), 0.f);
    hv.y = fmaxf(fmaf(ay, inv, bv.y), 0.f);
    hv.z = fmaxf(fmaf(az, inv, bv.z), 0.f);
    hv.w = fmaxf(fmaf(aw, inv, bv.w), 0.f);

    // h @ W2 (128->16) + layer-2 attention coefficients
    float asum = 0.f, dsum = 0.f;
#pragma unroll
    for (int c = 0; c < CC; c++) {
        float4 wv = *(const float4*)&w2s[c * HD + lane * 4];
        float pp = hv.x * wv.x + hv.y * wv.y + hv.z * wv.z + hv.w * wv.w;
#pragma unroll
        for (int off = 16; off; off >>= 1)
            pp += __shfl_down_sync(0xffffffffu, pp, off);
        if (lane == 0) {
            g_h2h[n * CC + c] = __float2half(pp);
            asum = fmaf(pp, as2[c], asum);
            dsum = fmaf(pp, ad2[c], dsum);
        }
    }
    if (lane == 0) {
        g_asrc2[n] = asum;
        g_adst2[n] = dsum;
    }
}

// ------------------------- layer-2 aggregation + fused bias/log_softmax -------------------------
__global__ void k_agg2(const float* __restrict__ b2, float* __restrict__ out) {
    int t = blockIdx.x * blockDim.x + threadIdx.x;
    int n = t >> 2;
    bool valid = n < NN;
    if (n >= NN) n = NN - 1;   // keep all lanes active for shfl
    int j = t & 3;
    const float adst = g_adst2[n];
    int p = g_rowptr[n], p1 = g_rowptr[n + 1];
    float ax = 0.f, ay = 0.f, az = 0.f, aw = 0.f, den = 0.f;
    for (; p + 4 <= p1; p += 4) {
        int s0 = g_csrc[p], s1 = g_csrc[p + 1], s2 = g_csrc[p + 2], s3 = g_csrc[p + 3];
        float a0 = g_asrc2[s0], a1 = g_asrc2[s1], a2 = g_asrc2[s2], a3 = g_asrc2[s3];
        uint2 u0 = *(const uint2*)&g_h2h[s0 * CC + j * 4];
        uint2 u1 = *(const uint2*)&g_h2h[s1 * CC + j * 4];
        uint2 u2 = *(const uint2*)&g_h2h[s2 * CC + j * 4];
        uint2 u3 = *(const uint2*)&g_h2h[s3 * CC + j * 4];
        float e0 = __expf(leaky(a0 + adst));
        float e1 = __expf(leaky(a1 + adst));
        float e2 = __expf(leaky(a2 + adst));
        float e3 = __expf(leaky(a3 + adst));
        den += e0 + e1 + e2 + e3;
        float vx, vy, vz, vw;
        h4_to_f4(u0, vx, vy, vz, vw);
        ax = fmaf(e0, vx, ax); ay = fmaf(e0, vy, ay); az = fmaf(e0, vz, az); aw = fmaf(e0, vw, aw);
        h4_to_f4(u1, vx, vy, vz, vw);
        ax = fmaf(e1, vx, ax); ay = fmaf(e1, vy, ay); az = fmaf(e1, vz, az); aw = fmaf(e1, vw, aw);
        h4_to_f4(u2, vx, vy, vz, vw);
        ax = fmaf(e2, vx, ax); ay = fmaf(e2, vy, ay); az = fmaf(e2, vz, az); aw = fmaf(e2, vw, aw);
        h4_to_f4(u3, vx, vy, vz, vw);
        ax = fmaf(e3, vx, ax); ay = fmaf(e3, vy, ay); az = fmaf(e3, vz, az); aw = fmaf(e3, vw, aw);
    }
    for (; p < p1; p++) {
        int s0 = g_csrc[p];
        float a0 = g_asrc2[s0];
        uint2 u0 = *(const uint2*)&g_h2h[s0 * CC + j * 4];
        float e0 = __expf(leaky(a0 + adst));
        den += e0;
        float vx, vy, vz, vw;
        h4_to_f4(u0, vx, vy, vz, vw);
        ax = fmaf(e0, vx, ax); ay = fmaf(e0, vy, ay); az = fmaf(e0, vz, az); aw = fmaf(e0, vw, aw);
    }
    float inv = __fdividef(1.f, den);
    float4 bb = *(const float4*)&b2[j * 4];
    float4 o = make_float4(fmaf(ax, inv, bb.x), fmaf(ay, inv, bb.y),
                           fmaf(az, inv, bb.z), fmaf(aw, inv, bb.w));
    // log_softmax over the 16 classes spread across the 4-lane group
    float m = fmaxf(fmaxf(o.x, o.y), fmaxf(o.z, o.w));
    m = fmaxf(m, __shfl_xor_sync(0xffffffffu, m, 1));
    m = fmaxf(m, __shfl_xor_sync(0xffffffffu, m, 2));
    float s = __expf(o.x - m) + __expf(o.y - m) + __expf(o.z - m) + __expf(o.w - m);
    s += __shfl_xor_sync(0xffffffffu, s, 1);
    s += __shfl_xor_sync(0xffffffffu, s, 2);
    float l = m + logf(s);
    o.x -= l; o.y -= l; o.z -= l; o.w -= l;
    if (valid) *(float4*)&out[n * CC + j * 4] = o;
}

// ------------------------- launch -------------------------
extern "C" void kernel_launch(void* const* d_in, const int* in_sizes, int n_in,
                              void* d_out, int out_size) {
    const float* x   = (const float*)d_in[0];
    const int*   ei  = (const int*)d_in[1];
    const float* W1  = (const float*)d_in[2];
    const float* as1 = (const float*)d_in[3];
    const float* ad1 = (const float*)d_in[4];
    const float* b1  = (const float*)d_in[5];
    const float* W2  = (const float*)d_in[6];
    const float* as2 = (const float*)d_in[7];
    const float* ad2 = (const float*)d_in[8];
    const float* b2  = (const float*)d_in[9];
    float* out = (float*)d_out;

    // one-time (non-device-memory) resources for fork/join capture
    static cudaStream_t s1 = nullptr;
    static cudaEvent_t evFork = nullptr, evJoin = nullptr;
    static void* degPtr = nullptr;
    if (!s1) {
        cudaStreamCreate(&s1);
        cudaEventCreateWithFlags(&evFork, cudaEventDisableTiming);
        cudaEventCreateWithFlags(&evJoin, cudaEventDisableTiming);
        cudaGetSymbolAddress(&degPtr, g_deg);
    }

    // fork: GEMM1 (depends only on x, W1) runs on s1 in parallel with graph prep
    cudaEventRecord(evFork, 0);
    cudaStreamWaitEvent(s1, evFork, 0);
    k_gemm1<<<(NN + 63) / 64, 256, 0, s1>>>(x, W1, as1, ad1);
    cudaEventRecord(evJoin, s1);

    // prep chain on the main (captured) stream
    cudaMemsetAsync(degPtr, 0, NN * sizeof(int));
    k_prep<<<(EPAD + 255) / 256, 256>>>(ei);
    k_scan1<<<NB1, 1024>>>();
    k_scan2<<<1, 64>>>();
    k_scan3<<<(NN + 255) / 256, 256>>>();
    k_scatter<<<(EPAD + 255) / 256, 256>>>();

    // join, then the dependent aggregation passes
    cudaStreamWaitEvent(0, evJoin, 0);
    k_agg1<<<(NN * 32 + 255) / 256, 256>>>(b1, W2, as2, ad2);
    k_agg2<<<(NN * 4 + 255) / 256, 256>>>(b2, out);
}